// round 4
// baseline (speedup 1.0000x reference)
#include <cuda_runtime.h>
#include <cuda_bf16.h>
#include <stdint.h>

#define N_NODES 100000
#define IN_DIM  128
#define HID_DIM 64
#define OUT_DIM 128

// Scratch (allocation-free rule: __device__ globals)
__device__ __align__(16) float g_dinv[N_NODES];
__device__ __align__(16) float g_hs [(size_t)N_NODES * HID_DIM];
__device__ __align__(16) float g_acc[(size_t)N_NODES * HID_DIM];

__device__ __forceinline__ void fma4(float4& a, float s, const float4& b) {
    a.x = fmaf(s, b.x, a.x);
    a.y = fmaf(s, b.y, a.y);
    a.z = fmaf(s, b.z, a.z);
    a.w = fmaf(s, b.w, a.w);
}

// ---------------------------------------------------------------- degree pass
__global__ void init_dinv_kernel(int n) {
    int i = blockIdx.x * blockDim.x + threadIdx.x;
    if (i < n) g_dinv[i] = 1.0f;  // self-loop
}

__global__ void deg_kernel(const int* __restrict__ dst, int e) {
    int i = blockIdx.x * blockDim.x + threadIdx.x;
    if (i < e) atomicAdd(&g_dinv[dst[i]], 1.0f);
}

__global__ void final_dinv_kernel(int n) {
    int i = blockIdx.x * blockDim.x + threadIdx.x;
    if (i < n) g_dinv[i] = rsqrtf(g_dinv[i]);
}

// ---------------------------------------------------------------- GEMM1
// hs[r][c] = dinv[r] * sum_k x[r][k]*Wc[k][c];  write to g_hs AND g_acc.
// Tile M=128, N=64 (all), K in chunks of 32. 256 threads = 8 warps.
// Warp tc owns cols [tc*8, tc*8+8)  -> W smem reads are pure broadcasts.
// Lane tr owns rows {tr, tr+32, tr+64, tr+96}; Xs row stride 9 float4 (odd)
// -> conflict-free LDS.128.
__global__ __launch_bounds__(256) void gemm1_kernel(const float* __restrict__ x,
                                                    const float* __restrict__ Wc,
                                                    int n) {
    __shared__ float4 Xs[128 * 9];   // 18 KB: 128 rows x 8 float4 (+1 pad)
    __shared__ float4 Ws[32 * 16];   // 8 KB:  32 k   x 64 cols
    const int t = threadIdx.x;
    const int rowBase = blockIdx.x * 128;
    const int tr = t & 31;
    const int tc = t >> 5;           // 0..7

    float4 acc[4][2];
    #pragma unroll
    for (int i = 0; i < 4; i++) {
        acc[i][0] = make_float4(0.f, 0.f, 0.f, 0.f);
        acc[i][1] = make_float4(0.f, 0.f, 0.f, 0.f);
    }

    const float4* Xg = (const float4*)x;
    const float4* Wg = (const float4*)Wc;

    for (int c = 0; c < 4; c++) {    // K chunks of 32
        // W chunk: 32x64 floats = 512 float4
        #pragma unroll
        for (int i = 0; i < 2; i++) {
            int idx = t + i * 256;
            int k = idx >> 4, col4 = idx & 15;
            Ws[idx] = Wg[(c * 32 + k) * 16 + col4];
        }
        // X chunk: 128 rows x 8 float4 = 1024 float4
        #pragma unroll
        for (int i = 0; i < 4; i++) {
            int idx = t + i * 256;
            int r = idx >> 3, q = idx & 7;
            int row = rowBase + r;
            float4 v = make_float4(0.f, 0.f, 0.f, 0.f);
            if (row < n) v = Xg[(size_t)row * 32 + c * 8 + q];
            Xs[r * 9 + q] = v;
        }
        __syncthreads();

        #pragma unroll
        for (int kq = 0; kq < 8; kq++) {
            float4 xv[4];
            #pragma unroll
            for (int i = 0; i < 4; i++) xv[i] = Xs[(tr + 32 * i) * 9 + kq];
            #pragma unroll
            for (int kk = 0; kk < 4; kk++) {
                float4 w0 = Ws[(kq * 4 + kk) * 16 + tc * 2];
                float4 w1 = Ws[(kq * 4 + kk) * 16 + tc * 2 + 1];
                #pragma unroll
                for (int i = 0; i < 4; i++) {
                    float s = (kk == 0) ? xv[i].x : (kk == 1) ? xv[i].y
                            : (kk == 2) ? xv[i].z : xv[i].w;
                    fma4(acc[i][0], s, w0);
                    fma4(acc[i][1], s, w1);
                }
            }
        }
        __syncthreads();
    }

    #pragma unroll
    for (int i = 0; i < 4; i++) {
        int row = rowBase + tr + 32 * i;
        if (row < n) {
            float dv = g_dinv[row];
            float4 a0 = acc[i][0], a1 = acc[i][1];
            a0.x *= dv; a0.y *= dv; a0.z *= dv; a0.w *= dv;
            a1.x *= dv; a1.y *= dv; a1.z *= dv; a1.w *= dv;
            size_t off = (size_t)row * 16 + tc * 2;   // float4 index
            ((float4*)g_hs)[off]      = a0;
            ((float4*)g_hs)[off + 1]  = a1;
            ((float4*)g_acc)[off]     = a0;
            ((float4*)g_acc)[off + 1] = a1;
        }
    }
}

// ---------------------------------------------------------------- edge scatter
// 8 threads per edge; each does 2x (LDG.128 gather + red.global.add.v4.f32)
__global__ __launch_bounds__(256) void scatter_kernel(const int* __restrict__ src,
                                                      const int* __restrict__ dst,
                                                      int e) {
    int gid = blockIdx.x * blockDim.x + threadIdx.x;
    int eid = gid >> 3;
    if (eid >= e) return;
    int g = gid & 7;
    int s = __ldg(&src[eid]);
    int d = __ldg(&dst[eid]);
    const float4* a = (const float4*)&g_hs[(size_t)s * HID_DIM + g * 8];
    float4 v0 = a[0];
    float4 v1 = a[1];
    float* p = &g_acc[(size_t)d * HID_DIM + g * 8];
    asm volatile("red.global.add.v4.f32 [%0], {%1,%2,%3,%4};"
                 :: "l"(p), "f"(v0.x), "f"(v0.y), "f"(v0.z), "f"(v0.w) : "memory");
    asm volatile("red.global.add.v4.f32 [%0], {%1,%2,%3,%4};"
                 :: "l"(p + 4), "f"(v1.x), "f"(v1.y), "f"(v1.z), "f"(v1.w) : "memory");
}

// ---------------------------------------------------------------- GEMM2 (fused)
// h2[r][k] = relu(dinv[r]*acc[r][k] + bconv[k]);  out = h2 @ Wlin + blin
// Tile M=128, N=128 (all), K=64 in 2 chunks of 32. 512 threads = 16 warps.
// Warp tc (0..15) owns cols [tc*8, tc*8+8); lane tr owns 4 rows.
__global__ __launch_bounds__(512) void gemm2_kernel(const float* __restrict__ Wlin,
                                                    const float* __restrict__ bconv,
                                                    const float* __restrict__ blin,
                                                    float* __restrict__ out,
                                                    int n) {
    __shared__ float4 Hs[128 * 9];   // 18 KB
    __shared__ float4 Ws[32 * 32];   // 16 KB: 32 k x 128 cols
    const int t = threadIdx.x;
    const int rowBase = blockIdx.x * 128;
    const int tr = t & 31;
    const int tc = t >> 5;           // 0..15

    float4 acc[4][2];
    #pragma unroll
    for (int i = 0; i < 4; i++) {
        acc[i][0] = make_float4(0.f, 0.f, 0.f, 0.f);
        acc[i][1] = make_float4(0.f, 0.f, 0.f, 0.f);
    }

    const float4* Wg = (const float4*)Wlin;

    for (int c = 0; c < 2; c++) {    // K chunks of 32
        // W chunk: 32x128 = 1024 float4
        #pragma unroll
        for (int i = 0; i < 2; i++) {
            int idx = t + i * 512;
            int k = idx >> 5, col4 = idx & 31;
            Ws[idx] = Wg[(c * 32 + k) * 32 + col4];
        }
        // H chunk: 128 rows x 8 float4, fused relu(dinv*acc + bconv)
        #pragma unroll
        for (int i = 0; i < 2; i++) {
            int idx = t + i * 512;
            int r = idx >> 3, q = idx & 7;
            int row = rowBase + r;
            float4 v = make_float4(0.f, 0.f, 0.f, 0.f);
            if (row < n) {
                v = *(const float4*)&g_acc[(size_t)row * HID_DIM + c * 32 + q * 4];
                float dv = g_dinv[row];
                float4 b = __ldg((const float4*)&bconv[c * 32 + q * 4]);
                v.x = fmaxf(fmaf(v.x, dv, b.x), 0.f);
                v.y = fmaxf(fmaf(v.y, dv, b.y), 0.f);
                v.z = fmaxf(fmaf(v.z, dv, b.z), 0.f);
                v.w = fmaxf(fmaf(v.w, dv, b.w), 0.f);
            }
            Hs[r * 9 + q] = v;
        }
        __syncthreads();

        #pragma unroll
        for (int kq = 0; kq < 8; kq++) {
            float4 xv[4];
            #pragma unroll
            for (int i = 0; i < 4; i++) xv[i] = Hs[(tr + 32 * i) * 9 + kq];
            #pragma unroll
            for (int kk = 0; kk < 4; kk++) {
                float4 w0 = Ws[(kq * 4 + kk) * 32 + tc * 2];
                float4 w1 = Ws[(kq * 4 + kk) * 32 + tc * 2 + 1];
                #pragma unroll
                for (int i = 0; i < 4; i++) {
                    float s = (kk == 0) ? xv[i].x : (kk == 1) ? xv[i].y
                            : (kk == 2) ? xv[i].z : xv[i].w;
                    fma4(acc[i][0], s, w0);
                    fma4(acc[i][1], s, w1);
                }
            }
        }
        __syncthreads();
    }

    float4 bl0 = __ldg((const float4*)&blin[tc * 8]);
    float4 bl1 = __ldg((const float4*)&blin[tc * 8 + 4]);
    #pragma unroll
    for (int i = 0; i < 4; i++) {
        int row = rowBase + tr + 32 * i;
        if (row < n) {
            float4 o0 = acc[i][0], o1 = acc[i][1];
            o0.x += bl0.x; o0.y += bl0.y; o0.z += bl0.z; o0.w += bl0.w;
            o1.x += bl1.x; o1.y += bl1.y; o1.z += bl1.z; o1.w += bl1.w;
            size_t off = (size_t)row * 32 + tc * 2;   // float4 index
            ((float4*)out)[off]     = o0;
            ((float4*)out)[off + 1] = o1;
        }
    }
}

// ---------------------------------------------------------------- launch
extern "C" void kernel_launch(void* const* d_in, const int* in_sizes, int n_in,
                              void* d_out, int out_size) {
    const float* x     = (const float*)d_in[0];
    const int*   ei    = (const int*)  d_in[1];
    const float* Wc    = (const float*)d_in[2];
    const float* bc    = (const float*)d_in[3];
    const float* Wl    = (const float*)d_in[4];
    const float* bl    = (const float*)d_in[5];
    float*       out   = (float*)d_out;

    const int n = in_sizes[0] / IN_DIM;      // 100000
    const int e = in_sizes[1] / 2;           // 1600000
    const int* src = ei;
    const int* dst = ei + e;

    init_dinv_kernel <<<(n + 255) / 256, 256>>>(n);
    deg_kernel       <<<(e + 255) / 256, 256>>>(dst, e);
    final_dinv_kernel<<<(n + 255) / 256, 256>>>(n);
    gemm1_kernel     <<<(n + 127) / 128, 256>>>(x, Wc, n);
    {
        long long threads = (long long)e * 8;
        int blocks = (int)((threads + 255) / 256);
        scatter_kernel<<<blocks, 256>>>(src, dst, e);
    }
    gemm2_kernel     <<<(n + 127) / 128, 512>>>(Wl, bc, bl, out, n);
}

// round 5
// speedup vs baseline: 1.3738x; 1.3738x over previous
#include <cuda_runtime.h>
#include <cuda_bf16.h>
#include <stdint.h>

#define N_NODES 100000
#define N_EDGES 1600000
#define IN_DIM  128
#define HID_DIM 64
#define OUT_DIM 128

// Scratch (allocation-free rule: __device__ globals)
__device__ __align__(16) float g_dinv[N_NODES];
__device__ __align__(16) float g_hs [(size_t)N_NODES * HID_DIM];   // (x@Wc)*dinv[row]
__device__ __align__(16) float g_acc[(size_t)N_NODES * HID_DIM];   // h2 after agg
__device__ int g_cnt[N_NODES];
__device__ int g_off[N_NODES];
__device__ int g_pos[N_NODES];
__device__ int g_bsum[128];
__device__ int g_csr[N_EDGES];

// ---------------------------------------------------------------- f32x2 helpers
__device__ __forceinline__ unsigned long long pack2(float x, float y) {
    unsigned long long r;
    asm("mov.b64 %0, {%1,%2};" : "=l"(r) : "f"(x), "f"(y));
    return r;
}
__device__ __forceinline__ float2 unpack2(unsigned long long v) {
    float2 r;
    asm("mov.b64 {%0,%1}, %2;" : "=f"(r.x), "=f"(r.y) : "l"(v));
    return r;
}
__device__ __forceinline__ void ffma2(unsigned long long& d, unsigned long long a,
                                      unsigned long long b) {
    asm("fma.rn.f32x2 %0, %1, %2, %0;" : "+l"(d) : "l"(a), "l"(b));
}
__device__ __forceinline__ unsigned long long mul2(unsigned long long a,
                                                   unsigned long long b) {
    unsigned long long d;
    asm("mul.rn.f32x2 %0, %1, %2;" : "=l"(d) : "l"(a), "l"(b));
    return d;
}
__device__ __forceinline__ unsigned long long add2(unsigned long long a,
                                                   unsigned long long b) {
    unsigned long long d;
    asm("add.rn.f32x2 %0, %1, %2;" : "=l"(d) : "l"(a), "l"(b));
    return d;
}

// ---------------------------------------------------------------- CSR build
__global__ void zero_kernel(int n) {
    int i = blockIdx.x * blockDim.x + threadIdx.x;
    if (i < n) { g_cnt[i] = 0; g_pos[i] = 0; }
}

__global__ void cnt_kernel(const int* __restrict__ dst, int e) {
    int i = blockIdx.x * blockDim.x + threadIdx.x;
    if (i < e) atomicAdd(&g_cnt[dst[i]], 1);
}

// exclusive scan, stage 1: per-block (1024) scan + block sums
__global__ __launch_bounds__(1024) void scan1_kernel(int n) {
    __shared__ int sh[1024];
    int t = threadIdx.x;
    int i = blockIdx.x * 1024 + t;
    int v = (i < n) ? g_cnt[i] : 0;
    sh[t] = v;
    __syncthreads();
    #pragma unroll
    for (int d = 1; d < 1024; d <<= 1) {
        int u = (t >= d) ? sh[t - d] : 0;
        __syncthreads();
        sh[t] += u;
        __syncthreads();
    }
    if (i < n) g_off[i] = sh[t] - v;               // exclusive
    if (t == 1023) g_bsum[blockIdx.x] = sh[1023];  // block total
}

// stage 2: scan block sums (nb <= 128), one block of 128 threads
__global__ void scan2_kernel(int nb) {
    __shared__ int sh[128];
    int t = threadIdx.x;
    int v = (t < nb) ? g_bsum[t] : 0;
    sh[t] = v;
    __syncthreads();
    #pragma unroll
    for (int d = 1; d < 128; d <<= 1) {
        int u = (t >= d) ? sh[t - d] : 0;
        __syncthreads();
        sh[t] += u;
        __syncthreads();
    }
    if (t < nb) g_bsum[t] = sh[t] - v;
}

// stage 3: add block offsets; also compute dinv = rsqrt(deg+1)
__global__ void scan3_kernel(int n) {
    int i = blockIdx.x * blockDim.x + threadIdx.x;
    if (i < n) {
        g_off[i] += g_bsum[i >> 10];
        g_dinv[i] = rsqrtf((float)g_cnt[i] + 1.0f);
    }
}

__global__ void fill_kernel(const int* __restrict__ src,
                            const int* __restrict__ dst, int e) {
    int i = blockIdx.x * blockDim.x + threadIdx.x;
    if (i < e) {
        int d = dst[i];
        int p = g_off[d] + atomicAdd(&g_pos[d], 1);
        g_csr[p] = src[i];
    }
}

// ---------------------------------------------------------------- GEMM1 (f32x2)
// hs[r][c] = dinv[r] * sum_k x[r][k]*Wc[k][c].  Tile M=128, N=64, K chunks of 32.
// 256 threads = 8 warps; warp tc owns cols [tc*8, tc*8+8) (W reads broadcast);
// lane tr owns rows {tr, tr+32, tr+64, tr+96}.
__global__ __launch_bounds__(256) void gemm1_kernel(const float* __restrict__ x,
                                                    const float* __restrict__ Wc,
                                                    int n) {
    __shared__ float4 Xs[128 * 9];
    __shared__ float4 Ws[32 * 16];
    const int t = threadIdx.x;
    const int rowBase = blockIdx.x * 128;
    const int tr = t & 31;
    const int tc = t >> 5;

    unsigned long long acc[4][4];  // 4 rows x 4 col-pairs (8 cols)
    #pragma unroll
    for (int i = 0; i < 4; i++)
        #pragma unroll
        for (int c2 = 0; c2 < 4; c2++) acc[i][c2] = 0ull;

    const float4* Xg = (const float4*)x;
    const float4* Wg = (const float4*)Wc;

    for (int c = 0; c < 4; c++) {
        #pragma unroll
        for (int i = 0; i < 2; i++) {
            int idx = t + i * 256;
            int k = idx >> 4, col4 = idx & 15;
            Ws[idx] = Wg[(c * 32 + k) * 16 + col4];
        }
        #pragma unroll
        for (int i = 0; i < 4; i++) {
            int idx = t + i * 256;
            int r = idx >> 3, q = idx & 7;
            int row = rowBase + r;
            float4 v = make_float4(0.f, 0.f, 0.f, 0.f);
            if (row < n) v = Xg[(size_t)row * 32 + c * 8 + q];
            Xs[r * 9 + q] = v;
        }
        __syncthreads();

        #pragma unroll
        for (int kq = 0; kq < 8; kq++) {
            float4 xv[4];
            #pragma unroll
            for (int i = 0; i < 4; i++) xv[i] = Xs[(tr + 32 * i) * 9 + kq];
            #pragma unroll
            for (int kk = 0; kk < 4; kk++) {
                float4 w0 = Ws[(kq * 4 + kk) * 16 + tc * 2];
                float4 w1 = Ws[(kq * 4 + kk) * 16 + tc * 2 + 1];
                unsigned long long wp0 = pack2(w0.x, w0.y);
                unsigned long long wp1 = pack2(w0.z, w0.w);
                unsigned long long wp2 = pack2(w1.x, w1.y);
                unsigned long long wp3 = pack2(w1.z, w1.w);
                #pragma unroll
                for (int i = 0; i < 4; i++) {
                    float s = (kk == 0) ? xv[i].x : (kk == 1) ? xv[i].y
                            : (kk == 2) ? xv[i].z : xv[i].w;
                    unsigned long long ss = pack2(s, s);
                    ffma2(acc[i][0], ss, wp0);
                    ffma2(acc[i][1], ss, wp1);
                    ffma2(acc[i][2], ss, wp2);
                    ffma2(acc[i][3], ss, wp3);
                }
            }
        }
        __syncthreads();
    }

    #pragma unroll
    for (int i = 0; i < 4; i++) {
        int row = rowBase + tr + 32 * i;
        if (row < n) {
            float dv = g_dinv[row];
            unsigned long long dd = pack2(dv, dv);
            float2 a = unpack2(mul2(acc[i][0], dd));
            float2 b = unpack2(mul2(acc[i][1], dd));
            float2 cc = unpack2(mul2(acc[i][2], dd));
            float2 d = unpack2(mul2(acc[i][3], dd));
            size_t off = (size_t)row * 16 + tc * 2;
            ((float4*)g_hs)[off]     = make_float4(a.x, a.y, b.x, b.y);
            ((float4*)g_hs)[off + 1] = make_float4(cc.x, cc.y, d.x, d.y);
        }
    }
}

// ---------------------------------------------------------------- aggregate
// 16 threads per node (one float4 chunk each); acc starts at self row;
// sum neighbor rows from CSR; h2 = relu(dinv*acc + bconv) -> g_acc.
__global__ __launch_bounds__(256) void agg_kernel(const float* __restrict__ bconv,
                                                  int n) {
    const int t = threadIdx.x;
    const int node = blockIdx.x * 16 + (t >> 4);
    const int c = t & 15;
    if (node >= n) return;

    const float4* hs4 = (const float4*)g_hs;
    float4 a0 = hs4[(size_t)node * 16 + c];      // self-loop message
    float4 a1 = make_float4(0.f, 0.f, 0.f, 0.f);

    int beg = g_off[node];
    int end = beg + g_cnt[node];
    int j = beg;
    for (; j + 1 < end; j += 2) {
        int s0 = g_csr[j];
        int s1 = g_csr[j + 1];
        float4 v0 = hs4[(size_t)s0 * 16 + c];
        float4 v1 = hs4[(size_t)s1 * 16 + c];
        a0.x += v0.x; a0.y += v0.y; a0.z += v0.z; a0.w += v0.w;
        a1.x += v1.x; a1.y += v1.y; a1.z += v1.z; a1.w += v1.w;
    }
    if (j < end) {
        int s0 = g_csr[j];
        float4 v0 = hs4[(size_t)s0 * 16 + c];
        a0.x += v0.x; a0.y += v0.y; a0.z += v0.z; a0.w += v0.w;
    }

    float dv = g_dinv[node];
    float4 b = __ldg((const float4*)&bconv[c * 4]);
    float4 r;
    r.x = fmaxf(fmaf(a0.x + a1.x, dv, b.x), 0.f);
    r.y = fmaxf(fmaf(a0.y + a1.y, dv, b.y), 0.f);
    r.z = fmaxf(fmaf(a0.z + a1.z, dv, b.z), 0.f);
    r.w = fmaxf(fmaf(a0.w + a1.w, dv, b.w), 0.f);
    ((float4*)g_acc)[(size_t)node * 16 + c] = r;
}

// ---------------------------------------------------------------- GEMM2 (f32x2)
// out = h2 @ Wlin + blin.  Tile M=64, N=128, K=64 in 2 chunks of 32.
// 256 threads = 8 warps; warp tc owns cols [tc*16, tc*16+16); lane tr rows {tr, tr+32}.
__global__ __launch_bounds__(256) void gemm2_kernel(const float* __restrict__ Wlin,
                                                    const float* __restrict__ blin,
                                                    float* __restrict__ out,
                                                    int n) {
    __shared__ float4 Hs[64 * 9];    // 9 KB
    __shared__ float4 Ws[32 * 32];   // 16 KB
    const int t = threadIdx.x;
    const int rowBase = blockIdx.x * 64;
    const int tr = t & 31;
    const int tc = t >> 5;

    unsigned long long acc[2][8];    // 2 rows x 8 col-pairs (16 cols)
    #pragma unroll
    for (int i = 0; i < 2; i++)
        #pragma unroll
        for (int c2 = 0; c2 < 8; c2++) acc[i][c2] = 0ull;

    const float4* Wg = (const float4*)Wlin;
    const float4* Hg = (const float4*)g_acc;

    for (int c = 0; c < 2; c++) {
        #pragma unroll
        for (int i = 0; i < 4; i++) {
            int idx = t + i * 256;
            int k = idx >> 5, col4 = idx & 31;
            Ws[idx] = Wg[(c * 32 + k) * 32 + col4];
        }
        #pragma unroll
        for (int i = 0; i < 2; i++) {
            int idx = t + i * 256;
            int r = idx >> 3, q = idx & 7;
            int row = rowBase + r;
            float4 v = make_float4(0.f, 0.f, 0.f, 0.f);
            if (row < n) v = Hg[(size_t)row * 16 + c * 8 + q];
            Hs[r * 9 + q] = v;
        }
        __syncthreads();

        #pragma unroll
        for (int kq = 0; kq < 8; kq++) {
            float4 xv[2];
            #pragma unroll
            for (int i = 0; i < 2; i++) xv[i] = Hs[(tr + 32 * i) * 9 + kq];
            #pragma unroll
            for (int kk = 0; kk < 4; kk++) {
                unsigned long long wp[8];
                #pragma unroll
                for (int m = 0; m < 4; m++) {
                    float4 w = Ws[(kq * 4 + kk) * 32 + tc * 4 + m];
                    wp[m * 2]     = pack2(w.x, w.y);
                    wp[m * 2 + 1] = pack2(w.z, w.w);
                }
                #pragma unroll
                for (int i = 0; i < 2; i++) {
                    float s = (kk == 0) ? xv[i].x : (kk == 1) ? xv[i].y
                            : (kk == 2) ? xv[i].z : xv[i].w;
                    unsigned long long ss = pack2(s, s);
                    #pragma unroll
                    for (int c2 = 0; c2 < 8; c2++) ffma2(acc[i][c2], ss, wp[c2]);
                }
            }
        }
        __syncthreads();
    }

    unsigned long long blp[8];
    {
        #pragma unroll
        for (int m = 0; m < 4; m++) {
            float4 b = __ldg((const float4*)&blin[tc * 16 + m * 4]);
            blp[m * 2]     = pack2(b.x, b.y);
            blp[m * 2 + 1] = pack2(b.z, b.w);
        }
    }
    #pragma unroll
    for (int i = 0; i < 2; i++) {
        int row = rowBase + tr + 32 * i;
        if (row < n) {
            size_t off = (size_t)row * 32 + tc * 4;
            #pragma unroll
            for (int m = 0; m < 4; m++) {
                float2 lo = unpack2(add2(acc[i][m * 2],     blp[m * 2]));
                float2 hi = unpack2(add2(acc[i][m * 2 + 1], blp[m * 2 + 1]));
                ((float4*)out)[off + m] = make_float4(lo.x, lo.y, hi.x, hi.y);
            }
        }
    }
}

// ---------------------------------------------------------------- launch
extern "C" void kernel_launch(void* const* d_in, const int* in_sizes, int n_in,
                              void* d_out, int out_size) {
    const float* x  = (const float*)d_in[0];
    const int*   ei = (const int*)  d_in[1];
    const float* Wc = (const float*)d_in[2];
    const float* bc = (const float*)d_in[3];
    const float* Wl = (const float*)d_in[4];
    const float* bl = (const float*)d_in[5];
    float*       out = (float*)d_out;

    const int n = in_sizes[0] / IN_DIM;      // 100000
    const int e = in_sizes[1] / 2;           // 1600000
    const int* src = ei;
    const int* dst = ei + e;
    const int nb = (n + 1023) >> 10;         // scan blocks (98)

    zero_kernel <<<(n + 255) / 256, 256>>>(n);
    cnt_kernel  <<<(e + 255) / 256, 256>>>(dst, e);
    scan1_kernel<<<nb, 1024>>>(n);
    scan2_kernel<<<1, 128>>>(nb);
    scan3_kernel<<<(n + 255) / 256, 256>>>(n);
    fill_kernel <<<(e + 255) / 256, 256>>>(src, dst, e);
    gemm1_kernel<<<(n + 127) / 128, 256>>>(x, Wc, n);
    agg_kernel  <<<(n + 15) / 16, 256>>>(bc, n);
    gemm2_kernel<<<(n + 63) / 64, 256>>>(Wl, bl, out, n);
}